// round 1
// baseline (speedup 1.0000x reference)
#include <cuda_runtime.h>
#include <math.h>

// Problem constants (fixed by setup_inputs)
#define XY 10
#define Zdim 5
#define S 500
#define NT 10000
#define Bsz 32
#define Tlen 40
#define Llen 20
#define NEGV (-1e9f)

// Scratch: transposed emissions [NT][S] = 20 MB (static device global, allowed)
__device__ float g_emT[NT * S];

// ---------------------------------------------------------------------------
// Kernel 1: transpose log_emissions [S][NT] -> g_emT [NT][S]
// ---------------------------------------------------------------------------
__global__ void transpose_kernel(const float* __restrict__ in) {
    __shared__ float tile[32][33];
    int x = blockIdx.x * 32 + threadIdx.x;  // NT dim
    int y = blockIdx.y * 32 + threadIdx.y;  // S dim
#pragma unroll
    for (int j = 0; j < 32; j += 8) {
        if (x < NT && (y + j) < S)
            tile[threadIdx.y + j][threadIdx.x] = in[(y + j) * NT + x];
    }
    __syncthreads();
    x = blockIdx.y * 32 + threadIdx.x;      // S dim in output
    y = blockIdx.x * 32 + threadIdx.y;      // NT dim in output
#pragma unroll
    for (int j = 0; j < 32; j += 8) {
        if (x < S && (y + j) < NT)
            g_emT[(y + j) * S + x] = tile[threadIdx.x][threadIdx.y + j];
    }
}

// ---------------------------------------------------------------------------
// Kernel 2: emission log-probs. em[t,b,s] = sum_l emT[tok[b,t,l]][s]
// Written directly into d_out[t*B*S + b*S + s] (recursion adds in-place later).
// ---------------------------------------------------------------------------
__global__ void em_kernel(const int* __restrict__ stories, float* __restrict__ out) {
    int bt = blockIdx.x;          // 0..B*T-1
    int b = bt / Tlen;
    int t = bt % Tlen;
    int s = threadIdx.x;          // 512 threads, s < S active
    if (s >= S) return;
    const int base = (b * Tlen + t) * Llen;
    float sum = 0.0f;
#pragma unroll
    for (int l = 0; l < Llen; l++) {
        int tok = __ldg(&stories[base + l]);   // broadcast within warp
        sum += __ldg(&g_emT[tok * S + s]);     // coalesced across s
    }
    out[(t * Bsz + b) * S + s] = sum;
}

// ---------------------------------------------------------------------------
// Kernel 3: forward recursion. One block per story b; alpha double-buffered
// in shared memory; 7-sparse transition stencil held in registers.
// ---------------------------------------------------------------------------
__global__ void __launch_bounds__(512, 1) forward_kernel(
    const float* __restrict__ prior,
    const float* __restrict__ logT,
    float* __restrict__ out)
{
    __shared__ float buf[2][512];
    const int s = threadIdx.x;
    const int b = blockIdx.x;
    const bool act = (s < S);

    // Per-thread sparse transition row: weights + neighbor indices
    float w[7];
    int   nb[7];
    if (act) {
        int z = s / (XY * XY);
        int r = s % (XY * XY);
        int y = r / XY;
        int x = r % XY;
        const float* row = logT + (long)s * S;
        // offsets: self, +x, -x, +y, -y, +z, +2z (columns j of row s)
        bool v1 = (x + 1 < XY), v2 = (x - 1 >= 0);
        bool v3 = (y + 1 < XY), v4 = (y - 1 >= 0);
        bool v5 = (z + 1 < Zdim), v6 = (z + 2 < Zdim);
        nb[0] = s;                     w[0] = __ldg(&row[s]);
        nb[1] = v1 ? s + 1   : s;      w[1] = v1 ? __ldg(&row[s + 1])   : NEGV;
        nb[2] = v2 ? s - 1   : s;      w[2] = v2 ? __ldg(&row[s - 1])   : NEGV;
        nb[3] = v3 ? s + XY  : s;      w[3] = v3 ? __ldg(&row[s + XY])  : NEGV;
        nb[4] = v4 ? s - XY  : s;      w[4] = v4 ? __ldg(&row[s - XY])  : NEGV;
        nb[5] = v5 ? s + XY*XY   : s;  w[5] = v5 ? __ldg(&row[s + XY*XY])   : NEGV;
        nb[6] = v6 ? s + 2*XY*XY : s;  w[6] = v6 ? __ldg(&row[s + 2*XY*XY]) : NEGV;
    }

    // t = 0: alpha0 = em0 + prior
    float a0 = 0.0f;
    if (act) {
        a0 = out[(0 * Bsz + b) * S + s] + __ldg(&prior[s]);
        out[(0 * Bsz + b) * S + s] = a0;
        buf[0][s] = a0;
    }
    __syncthreads();

    // Prefetch em for t=1
    float em_next = 0.0f;
    if (act) em_next = out[(1 * Bsz + b) * S + s];

    int cur = 0;
    for (int t = 1; t < Tlen; t++) {
        float em_t = em_next;
        // issue next-step em load early to hide latency behind compute
        if (act && t + 1 < Tlen) em_next = out[((t + 1) * Bsz + b) * S + s];

        if (act) {
            float v[7];
            float m = NEGV;
#pragma unroll
            for (int k = 0; k < 7; k++) {
                v[k] = w[k] + buf[cur][nb[k]];
                m = fmaxf(m, v[k]);
            }
            float sum = 0.0f;
#pragma unroll
            for (int k = 0; k < 7; k++)
                sum += __expf(v[k] - m);
            float a = em_t + m + __logf(sum);
            out[(t * Bsz + b) * S + s] = a;
            buf[cur ^ 1][s] = a;
        }
        __syncthreads();
        cur ^= 1;
    }
}

// ---------------------------------------------------------------------------
extern "C" void kernel_launch(void* const* d_in, const int* in_sizes, int n_in,
                              void* d_out, int out_size) {
    const float* log_priors      = (const float*)d_in[0];
    const float* log_transitions = (const float*)d_in[1];
    const float* log_emissions   = (const float*)d_in[2];
    const int*   stories         = (const int*)d_in[3];
    float* out = (float*)d_out;

    // 1) transpose emissions
    dim3 tb(32, 8);
    dim3 tg((NT + 31) / 32, (S + 31) / 32);
    transpose_kernel<<<tg, tb>>>(log_emissions);

    // 2) emission sums into d_out
    em_kernel<<<Bsz * Tlen, 512>>>(stories, out);

    // 3) forward recursion (in-place on d_out)
    forward_kernel<<<Bsz, 512>>>(log_priors, log_transitions, out);
}